// round 4
// baseline (speedup 1.0000x reference)
#include <cuda_runtime.h>
#include <cuda_bf16.h>
#include <cstdint>

#define N_NODES 50000
#define N_EDGES 800000
#define DIM     128
#define LN_EPS  1e-5f

// ---------------- device scratch ----------------
__device__ float g_h[N_NODES * DIM];
__device__ float g_buf[N_NODES * DIM];
__device__ int   g_deg[N_NODES];
__device__ int   g_off[N_NODES + 1];
__device__ int   g_cursor[N_NODES];
__device__ int2  g_edge[N_EDGES];        // {src, bit-cast edge weight}

// ---------------- f32x2 packed math helpers ----------------
__device__ __forceinline__ unsigned long long pack2(float a, float b) {
    unsigned long long r;
    asm("mov.b64 %0, {%1,%2};" : "=l"(r) : "f"(a), "f"(b));
    return r;
}
__device__ __forceinline__ unsigned long long fma2(unsigned long long x,
                                                   unsigned long long y,
                                                   unsigned long long z) {
    unsigned long long r;
    asm("fma.rn.f32x2 %0, %1, %2, %3;" : "=l"(r) : "l"(x), "l"(y), "l"(z));
    return r;
}
__device__ __forceinline__ float2 unpack2(unsigned long long v) {
    float2 f;
    asm("mov.b64 {%0,%1}, %2;" : "=f"(f.x), "=f"(f.y) : "l"(v));
    return f;
}

// ---------------- CSR build ----------------
__global__ void count_kernel(const int* __restrict__ eidx, int E) {
    int e = blockIdx.x * blockDim.x + threadIdx.x;
    if (e < E) atomicAdd(&g_deg[eidx[E + e]], 1);
}

// Single-block scan, 4 elements/thread (chunk = 4096).
__global__ void scan_kernel(int n) {
    __shared__ int wsum[32];
    int tid = threadIdx.x, lane = tid & 31, wid = tid >> 5;
    int carry = 0;
    for (int base = 0; base < n; base += 4096) {
        int i0 = base + tid * 4;
        int v0 = (i0 + 0 < n) ? g_deg[i0 + 0] : 0;
        int v1 = (i0 + 1 < n) ? g_deg[i0 + 1] : 0;
        int v2 = (i0 + 2 < n) ? g_deg[i0 + 2] : 0;
        int v3 = (i0 + 3 < n) ? g_deg[i0 + 3] : 0;
        int tsum = v0 + v1 + v2 + v3;
        int x = tsum;
        #pragma unroll
        for (int o = 1; o < 32; o <<= 1) {
            int y = __shfl_up_sync(0xffffffffu, x, o);
            if (lane >= o) x += y;
        }
        if (lane == 31) wsum[wid] = x;
        __syncthreads();
        if (wid == 0) {
            int s = wsum[lane];
            #pragma unroll
            for (int o = 1; o < 32; o <<= 1) {
                int y = __shfl_up_sync(0xffffffffu, s, o);
                if (lane >= o) s += y;
            }
            wsum[lane] = s;
        }
        __syncthreads();
        int run = carry + (x - tsum) + (wid > 0 ? wsum[wid - 1] : 0);
        if (i0 + 0 < n) { g_off[i0 + 0] = run; g_cursor[i0 + 0] = run; } run += v0;
        if (i0 + 1 < n) { g_off[i0 + 1] = run; g_cursor[i0 + 1] = run; } run += v1;
        if (i0 + 2 < n) { g_off[i0 + 2] = run; g_cursor[i0 + 2] = run; } run += v2;
        if (i0 + 3 < n) { g_off[i0 + 3] = run; g_cursor[i0 + 3] = run; }
        carry += wsum[31];
        __syncthreads();
    }
    if (tid == 0) g_off[n] = carry;
}

__global__ void fill_kernel(const int* __restrict__ eidx,
                            const float* __restrict__ ew, int E) {
    int e = blockIdx.x * blockDim.x + threadIdx.x;
    if (e < E) {
        int s = eidx[e];
        int d = eidx[E + e];
        int p = atomicAdd(&g_cursor[d], 1);
        g_edge[p] = make_int2(s, __float_as_int(ew[e]));   // one 8B scatter
    }
}

// ---------------- GEMM: H = X @ W,  4 rows per warp, f32x2 FMA ----------------
__global__ __launch_bounds__(256) void gemm128_kernel(
        const float* __restrict__ X, const float* __restrict__ W,
        float* __restrict__ H, int nrows) {
    __shared__ float xs[32][DIM];   // 16 KB
    int tid = threadIdx.x, lane = tid & 31, w = tid >> 5;
    int blockRow = blockIdx.x * 32;

    #pragma unroll
    for (int r = 0; r < 32; r += 8) {
        int row = blockRow + r + w;
        if (row < nrows)
            ((float4*)xs[r + w])[lane] = ((const float4*)(X + (size_t)row * DIM))[lane];
    }
    __syncthreads();

    int myRow0 = blockRow + w * 4;
    const ulonglong2* Wv = (const ulonglong2*)W;

    unsigned long long a01[4], a23[4];
    #pragma unroll
    for (int r = 0; r < 4; ++r) { a01[r] = pack2(0.f, 0.f); a23[r] = a01[r]; }

    #pragma unroll 4
    for (int k4 = 0; k4 < 32; ++k4) {
        ulonglong2 w0 = __ldg(&Wv[(4 * k4 + 0) * 32 + lane]);
        ulonglong2 w1 = __ldg(&Wv[(4 * k4 + 1) * 32 + lane]);
        ulonglong2 w2 = __ldg(&Wv[(4 * k4 + 2) * 32 + lane]);
        ulonglong2 w3 = __ldg(&Wv[(4 * k4 + 3) * 32 + lane]);
        #pragma unroll
        for (int r = 0; r < 4; ++r) {
            float4 a = ((const float4*)xs[w * 4 + r])[k4];
            unsigned long long ax = pack2(a.x, a.x);
            unsigned long long ay = pack2(a.y, a.y);
            unsigned long long az = pack2(a.z, a.z);
            unsigned long long aw = pack2(a.w, a.w);
            a01[r] = fma2(w0.x, ax, a01[r]);  a23[r] = fma2(w0.y, ax, a23[r]);
            a01[r] = fma2(w1.x, ay, a01[r]);  a23[r] = fma2(w1.y, ay, a23[r]);
            a01[r] = fma2(w2.x, az, a01[r]);  a23[r] = fma2(w2.y, az, a23[r]);
            a01[r] = fma2(w3.x, aw, a01[r]);  a23[r] = fma2(w3.y, aw, a23[r]);
        }
    }

    #pragma unroll
    for (int r = 0; r < 4; ++r) {
        int row = myRow0 + r;
        if (row < nrows) {
            float2 lo = unpack2(a01[r]), hi = unpack2(a23[r]);
            ((float4*)(H + (size_t)row * DIM))[lane] =
                make_float4(lo.x, lo.y, hi.x, hi.y);
        }
    }
}

// ---------------- Aggregate + bias + LayerNorm + ReLU (fused) ----------------
// One warp per destination node; lane l owns columns 4l..4l+3. Unroll 8.
__global__ __launch_bounds__(256) void agg_ln_relu_kernel(
        const float* __restrict__ H,
        const float* __restrict__ bias,
        const float* __restrict__ gamma,
        const float* __restrict__ beta,
        float* __restrict__ out, int nrows) {
    int w = threadIdx.x >> 5, lane = threadIdx.x & 31;
    int node = blockIdx.x * 8 + w;
    if (node >= nrows) return;

    int jb = g_off[node], je = g_off[node + 1];
    const float4* Hv = (const float4*)H;

    float4 acc = make_float4(0.f, 0.f, 0.f, 0.f);
    int j = jb;
    for (; j + 8 <= je; j += 8) {
        int2 p[8];
        #pragma unroll
        for (int u = 0; u < 8; ++u) p[u] = __ldg(&g_edge[j + u]);
        float4 hv[8];
        #pragma unroll
        for (int u = 0; u < 8; ++u)
            hv[u] = __ldg(&Hv[(size_t)p[u].x * 32 + lane]);
        #pragma unroll
        for (int u = 0; u < 8; ++u) {
            float e = __int_as_float(p[u].y);
            acc.x += e * hv[u].x; acc.y += e * hv[u].y;
            acc.z += e * hv[u].z; acc.w += e * hv[u].w;
        }
    }
    for (; j < je; ++j) {
        int2 p = __ldg(&g_edge[j]);
        float e = __int_as_float(p.y);
        float4 hv = __ldg(&Hv[(size_t)p.x * 32 + lane]);
        acc.x += e * hv.x; acc.y += e * hv.y;
        acc.z += e * hv.z; acc.w += e * hv.w;
    }

    float4 b4 = __ldg(&((const float4*)bias)[lane]);
    acc.x += b4.x; acc.y += b4.y; acc.z += b4.z; acc.w += b4.w;

    float s1 = acc.x + acc.y + acc.z + acc.w;
    float s2 = acc.x * acc.x + acc.y * acc.y + acc.z * acc.z + acc.w * acc.w;
    #pragma unroll
    for (int o = 16; o > 0; o >>= 1) {
        s1 += __shfl_xor_sync(0xffffffffu, s1, o);
        s2 += __shfl_xor_sync(0xffffffffu, s2, o);
    }
    float mu  = s1 * (1.f / 128.f);
    float var = s2 * (1.f / 128.f) - mu * mu;
    float r   = rsqrtf(var + LN_EPS);

    float4 g4 = __ldg(&((const float4*)gamma)[lane]);
    float4 e4 = __ldg(&((const float4*)beta)[lane]);
    float4 y;
    y.x = fmaxf((acc.x - mu) * r * g4.x + e4.x, 0.f);
    y.y = fmaxf((acc.y - mu) * r * g4.y + e4.y, 0.f);
    y.z = fmaxf((acc.z - mu) * r * g4.z + e4.z, 0.f);
    y.w = fmaxf((acc.w - mu) * r * g4.w + e4.w, 0.f);
    ((float4*)(out + (size_t)node * DIM))[lane] = y;
}

// ---------------- launch ----------------
extern "C" void kernel_launch(void* const* d_in, const int* in_sizes, int n_in,
                              void* d_out, int out_size) {
    const float* x    = (const float*)d_in[0];
    const int*   eidx = (const int*)d_in[1];
    const float* ew   = (const float*)d_in[2];
    const float* W1   = (const float*)d_in[3];
    const float* b1   = (const float*)d_in[4];
    const float* W2   = (const float*)d_in[5];
    const float* b2   = (const float*)d_in[6];
    const float* g1   = (const float*)d_in[7];
    const float* be1  = (const float*)d_in[8];
    const float* g2   = (const float*)d_in[9];
    const float* be2  = (const float*)d_in[10];
    float* out = (float*)d_out;

    const int N = N_NODES;
    const int E = N_EDGES;

    float *h_p, *buf_p;
    int   *deg_p;
    cudaGetSymbolAddress((void**)&h_p,   g_h);
    cudaGetSymbolAddress((void**)&buf_p, g_buf);
    cudaGetSymbolAddress((void**)&deg_p, g_deg);

    // ---- CSR build ----
    cudaMemsetAsync(deg_p, 0, N * sizeof(int));
    count_kernel<<<(E + 255) / 256, 256>>>(eidx, E);
    scan_kernel<<<1, 1024>>>(N);
    fill_kernel<<<(E + 255) / 256, 256>>>(eidx, ew, E);

    const int gemm_blocks = (N + 31) / 32;
    const int agg_blocks  = (N + 7) / 8;

    gemm128_kernel<<<gemm_blocks, 256>>>(x, W1, h_p, N);
    agg_ln_relu_kernel<<<agg_blocks, 256>>>(h_p, b1, g1, be1, buf_p, N);

    gemm128_kernel<<<gemm_blocks, 256>>>(buf_p, W2, h_p, N);
    agg_ln_relu_kernel<<<agg_blocks, 256>>>(h_p, b2, g2, be2, out, N);
}